// round 1
// baseline (speedup 1.0000x reference)
#include <cuda_runtime.h>

#define H 128
#define TILE 128
#define AS_LD 132
#define NTHREADS 256

typedef unsigned long long ull;

#define MAXN_PAD 50176
__device__ float g_P[(size_t)MAXN_PAD * H];    // node_rep @ W1_top
__device__ float g_Q[(size_t)MAXN_PAD * H];    // node_rep @ W_lift
__device__ float g_acc[(size_t)MAXN_PAD * H];  // (1+eps1)*node_rep + scatter(edge_h)

__device__ __forceinline__ ull pk(float lo, float hi) {
    ull r; asm("mov.b64 %0, {%1,%2};" : "=l"(r) : "f"(lo), "f"(hi)); return r;
}
__device__ __forceinline__ float2 upk(ull v) {
    float2 f; asm("mov.b64 {%0,%1}, %2;" : "=f"(f.x), "=f"(f.y) : "l"(v)); return f;
}
__device__ __forceinline__ void fma2(ull& d, ull a, ull b) {
    asm("fma.rn.f32x2 %0, %1, %2, %0;" : "+l"(d) : "l"(a), "l"(b));
}
__device__ __forceinline__ void red_add_v4(float* p, float a, float b, float c, float d) {
    asm volatile("red.global.add.v4.f32 [%0], {%1,%2,%3,%4};"
                 :: "l"(p), "f"(a), "f"(b), "f"(c), "f"(d) : "memory");
}

// C[r0..r0+8, c0..c0+8] += AsT(k-major, [H][TILE+pad]) x Bs([H][H] row-major)
__device__ __forceinline__ void mm_tile(const float* __restrict__ AsT,
                                        const float* __restrict__ Bs,
                                        int r0, int c0, ull acc[8][4]) {
#pragma unroll 2
    for (int k = 0; k < H; k++) {
        float4 a0 = *(const float4*)&AsT[k * AS_LD + r0];
        float4 a1 = *(const float4*)&AsT[k * AS_LD + r0 + 4];
        float4 b0 = *(const float4*)&Bs[k * H + c0];
        float4 b1 = *(const float4*)&Bs[k * H + c0 + 4];
        ull bb0 = pk(b0.x, b0.y), bb1 = pk(b0.z, b0.w);
        ull bb2 = pk(b1.x, b1.y), bb3 = pk(b1.z, b1.w);
        float a[8] = { a0.x, a0.y, a0.z, a0.w, a1.x, a1.y, a1.z, a1.w };
#pragma unroll
        for (int i = 0; i < 8; i++) {
            ull aa = pk(a[i], a[i]);
            fma2(acc[i][0], aa, bb0);
            fma2(acc[i][1], aa, bb1);
            fma2(acc[i][2], aa, bb2);
            fma2(acc[i][3], aa, bb3);
        }
    }
}

__device__ __forceinline__ void zero_acc(ull acc[8][4]) {
#pragma unroll
    for (int i = 0; i < 8; i++)
#pragma unroll
        for (int j = 0; j < 4; j++) acc[i][j] = 0ULL;
}

// ---------------------------------------------------------------------------
// K0: P = node @ W1_top, Q = node @ W_lift, g_acc = (1+eps1)*node
// ---------------------------------------------------------------------------
extern "C" __global__ void __launch_bounds__(NTHREADS)
k_node_pre(const float* __restrict__ node, const float* __restrict__ W1,
           const float* __restrict__ Wlift, const float* __restrict__ eps1p, int N)
{
    extern __shared__ float sm[];
    float* AsT = sm;                    // [H][AS_LD]
    float* Ws1 = sm + TILE * AS_LD;     // W1 top rows [H][H]
    float* Ws2 = Ws1 + H * H;           // W_lift      [H][H]
    const int tid = threadIdx.x;
    const int base = blockIdx.x * TILE;
    const float s1 = 1.f + __ldg(eps1p);

    for (int i = tid; i < H * H / 4; i += NTHREADS) {
        ((float4*)Ws1)[i] = ((const float4*)W1)[i];       // W1 rows 0..127
        ((float4*)Ws2)[i] = ((const float4*)Wlift)[i];
    }
    for (int i4 = tid; i4 < TILE * (H / 4); i4 += NTHREADS) {
        int r = i4 >> 5, kc = (i4 & 31) << 2;
        int row = base + r;
        int rc = row < N ? row : N - 1;
        float4 v = *(const float4*)&node[(size_t)rc * H + kc];
        AsT[(kc + 0) * AS_LD + r] = v.x;
        AsT[(kc + 1) * AS_LD + r] = v.y;
        AsT[(kc + 2) * AS_LD + r] = v.z;
        AsT[(kc + 3) * AS_LD + r] = v.w;
        if (row < N) {
            float4 o = { s1 * v.x, s1 * v.y, s1 * v.z, s1 * v.w };
            *(float4*)&g_acc[(size_t)row * H + kc] = o;
        }
    }
    __syncthreads();

    const int r0 = (tid >> 4) * 8, c0 = (tid & 15) * 8;
    ull acc[8][4];

    zero_acc(acc);
    mm_tile(AsT, Ws1, r0, c0, acc);
#pragma unroll
    for (int i = 0; i < 8; i++) {
        int row = base + r0 + i;
        if (row < N) {
            float2 v0 = upk(acc[i][0]), v1 = upk(acc[i][1]);
            float2 v2 = upk(acc[i][2]), v3 = upk(acc[i][3]);
            float4 o0 = { v0.x, v0.y, v1.x, v1.y };
            float4 o1 = { v2.x, v2.y, v3.x, v3.y };
            *(float4*)&g_P[(size_t)row * H + c0] = o0;
            *(float4*)&g_P[(size_t)row * H + c0 + 4] = o1;
        }
    }

    zero_acc(acc);
    mm_tile(AsT, Ws2, r0, c0, acc);
#pragma unroll
    for (int i = 0; i < 8; i++) {
        int row = base + r0 + i;
        if (row < N) {
            float2 v0 = upk(acc[i][0]), v1 = upk(acc[i][1]);
            float2 v2 = upk(acc[i][2]), v3 = upk(acc[i][3]);
            float4 o0 = { v0.x, v0.y, v1.x, v1.y };
            float4 o1 = { v2.x, v2.y, v3.x, v3.y };
            *(float4*)&g_Q[(size_t)row * H + c0] = o0;
            *(float4*)&g_Q[(size_t)row * H + c0 + 4] = o1;
        }
    }
}

// ---------------------------------------------------------------------------
// K1: fused edge pipeline.
//   edge_h = relu(edge_rep @ W1_bot + P[src] + P[dst])
//   g_acc[src] += edge_h ; g_acc[dst] += edge_h          (vector red)
//   edge_out = relu((1+eps2)*(edge_h @ W_lift) + Q[src] + Q[dst])
// ---------------------------------------------------------------------------
extern "C" __global__ void __launch_bounds__(NTHREADS)
k_edge(const float* __restrict__ edge_rep, const int* __restrict__ srcI,
       const int* __restrict__ dstI, const float* __restrict__ W1,
       const float* __restrict__ Wlift, const float* __restrict__ eps2p,
       float* __restrict__ edge_out, int E)
{
    extern __shared__ float sm[];
    float* AsT = sm;                    // [H][AS_LD]
    float* Wb  = sm + TILE * AS_LD;     // W1 bottom rows
    float* Wl  = Wb + H * H;            // W_lift
    int*   sidx = (int*)(Wl + H * H);   // [2*TILE]
    const int tid = threadIdx.x;
    const int base = blockIdx.x * TILE;
    const float* W1b = W1 + H * H;      // rows 128..255 multiply edge_rep

    for (int i = tid; i < H * H / 4; i += NTHREADS) {
        ((float4*)Wb)[i] = ((const float4*)W1b)[i];
        ((float4*)Wl)[i] = ((const float4*)Wlift)[i];
    }
    for (int i = tid; i < TILE; i += NTHREADS) {
        int e = base + i; int ec = e < E ? e : E - 1;
        sidx[i] = srcI[ec];
        sidx[TILE + i] = dstI[ec];
    }
    for (int i4 = tid; i4 < TILE * (H / 4); i4 += NTHREADS) {
        int r = i4 >> 5, kc = (i4 & 31) << 2;
        int row = base + r; if (row >= E) row = E - 1;
        float4 v = *(const float4*)&edge_rep[(size_t)row * H + kc];
        AsT[(kc + 0) * AS_LD + r] = v.x;
        AsT[(kc + 1) * AS_LD + r] = v.y;
        AsT[(kc + 2) * AS_LD + r] = v.z;
        AsT[(kc + 3) * AS_LD + r] = v.w;
    }
    __syncthreads();

    const int r0 = (tid >> 4) * 8, c0 = (tid & 15) * 8;
    ull acc[8][4];

    zero_acc(acc);
    mm_tile(AsT, Wb, r0, c0, acc);

    // epilogue 1: add P gathers, relu, scatter, repack h into acc
#pragma unroll
    for (int i = 0; i < 8; i++) {
        int r = r0 + i;
        int s = sidx[r], d = sidx[TILE + r];
        const float4* Ps = (const float4*)&g_P[(size_t)s * H + c0];
        const float4* Pd = (const float4*)&g_P[(size_t)d * H + c0];
        float4 ps0 = __ldg(Ps), ps1 = __ldg(Ps + 1);
        float4 pd0 = __ldg(Pd), pd1 = __ldg(Pd + 1);
        float2 c01 = upk(acc[i][0]), c23 = upk(acc[i][1]);
        float2 c45 = upk(acc[i][2]), c67 = upk(acc[i][3]);
        float h0 = fmaxf(c01.x + ps0.x + pd0.x, 0.f);
        float h1 = fmaxf(c01.y + ps0.y + pd0.y, 0.f);
        float h2 = fmaxf(c23.x + ps0.z + pd0.z, 0.f);
        float h3 = fmaxf(c23.y + ps0.w + pd0.w, 0.f);
        float h4 = fmaxf(c45.x + ps1.x + pd1.x, 0.f);
        float h5 = fmaxf(c45.y + ps1.y + pd1.y, 0.f);
        float h6 = fmaxf(c67.x + ps1.z + pd1.z, 0.f);
        float h7 = fmaxf(c67.y + ps1.w + pd1.w, 0.f);
        if (base + r < E) {
            red_add_v4(&g_acc[(size_t)s * H + c0],     h0, h1, h2, h3);
            red_add_v4(&g_acc[(size_t)s * H + c0 + 4], h4, h5, h6, h7);
            red_add_v4(&g_acc[(size_t)d * H + c0],     h0, h1, h2, h3);
            red_add_v4(&g_acc[(size_t)d * H + c0 + 4], h4, h5, h6, h7);
        }
        acc[i][0] = pk(h0, h1); acc[i][1] = pk(h2, h3);
        acc[i][2] = pk(h4, h5); acc[i][3] = pk(h6, h7);
    }
    __syncthreads();   // everyone done reading AsT (edge_rep)

    // stash edge_h into AsT (k-major: k-dim = h column)
#pragma unroll
    for (int i = 0; i < 8; i++) {
        int r = r0 + i;
        float2 a = upk(acc[i][0]), b = upk(acc[i][1]);
        float2 c = upk(acc[i][2]), d2 = upk(acc[i][3]);
        AsT[(c0 + 0) * AS_LD + r] = a.x;
        AsT[(c0 + 1) * AS_LD + r] = a.y;
        AsT[(c0 + 2) * AS_LD + r] = b.x;
        AsT[(c0 + 3) * AS_LD + r] = b.y;
        AsT[(c0 + 4) * AS_LD + r] = c.x;
        AsT[(c0 + 5) * AS_LD + r] = c.y;
        AsT[(c0 + 6) * AS_LD + r] = d2.x;
        AsT[(c0 + 7) * AS_LD + r] = d2.y;
    }
    __syncthreads();

    ull acc2[8][4];
    zero_acc(acc2);
    mm_tile(AsT, Wl, r0, c0, acc2);

    const float s2 = 1.f + __ldg(eps2p);
#pragma unroll
    for (int i = 0; i < 8; i++) {
        int r = r0 + i;
        size_t row = (size_t)(base + r);
        if (base + r < E) {
            int s = sidx[r], d = sidx[TILE + r];
            float4 qs0 = __ldg((const float4*)&g_Q[(size_t)s * H + c0]);
            float4 qs1 = __ldg((const float4*)&g_Q[(size_t)s * H + c0 + 4]);
            float4 qd0 = __ldg((const float4*)&g_Q[(size_t)d * H + c0]);
            float4 qd1 = __ldg((const float4*)&g_Q[(size_t)d * H + c0 + 4]);
            float2 c01 = upk(acc2[i][0]), c23 = upk(acc2[i][1]);
            float2 c45 = upk(acc2[i][2]), c67 = upk(acc2[i][3]);
            float4 o0, o1;
            o0.x = fmaxf(fmaf(s2, c01.x, qs0.x + qd0.x), 0.f);
            o0.y = fmaxf(fmaf(s2, c01.y, qs0.y + qd0.y), 0.f);
            o0.z = fmaxf(fmaf(s2, c23.x, qs0.z + qd0.z), 0.f);
            o0.w = fmaxf(fmaf(s2, c23.y, qs0.w + qd0.w), 0.f);
            o1.x = fmaxf(fmaf(s2, c45.x, qs1.x + qd1.x), 0.f);
            o1.y = fmaxf(fmaf(s2, c45.y, qs1.y + qd1.y), 0.f);
            o1.z = fmaxf(fmaf(s2, c67.x, qs1.z + qd1.z), 0.f);
            o1.w = fmaxf(fmaf(s2, c67.y, qs1.w + qd1.w), 0.f);
            *(float4*)&edge_out[row * H + c0] = o0;
            *(float4*)&edge_out[row * H + c0 + 4] = o1;
        }
    }
}

// ---------------------------------------------------------------------------
// K2: node_out = relu(g_acc @ W2)
// ---------------------------------------------------------------------------
extern "C" __global__ void __launch_bounds__(NTHREADS)
k_node_out(const float* __restrict__ W2, float* __restrict__ node_out, int N)
{
    extern __shared__ float sm[];
    float* AsT = sm;
    float* Ws = sm + TILE * AS_LD;
    const int tid = threadIdx.x;
    const int base = blockIdx.x * TILE;

    for (int i = tid; i < H * H / 4; i += NTHREADS)
        ((float4*)Ws)[i] = ((const float4*)W2)[i];
    for (int i4 = tid; i4 < TILE * (H / 4); i4 += NTHREADS) {
        int r = i4 >> 5, kc = (i4 & 31) << 2;
        int row = base + r; if (row >= N) row = N - 1;
        float4 v = *(const float4*)&g_acc[(size_t)row * H + kc];
        AsT[(kc + 0) * AS_LD + r] = v.x;
        AsT[(kc + 1) * AS_LD + r] = v.y;
        AsT[(kc + 2) * AS_LD + r] = v.z;
        AsT[(kc + 3) * AS_LD + r] = v.w;
    }
    __syncthreads();

    const int r0 = (tid >> 4) * 8, c0 = (tid & 15) * 8;
    ull acc[8][4];
    zero_acc(acc);
    mm_tile(AsT, Ws, r0, c0, acc);
#pragma unroll
    for (int i = 0; i < 8; i++) {
        int row = base + r0 + i;
        if (row < N) {
            float2 v0 = upk(acc[i][0]), v1 = upk(acc[i][1]);
            float2 v2 = upk(acc[i][2]), v3 = upk(acc[i][3]);
            float4 o0 = { fmaxf(v0.x, 0.f), fmaxf(v0.y, 0.f), fmaxf(v1.x, 0.f), fmaxf(v1.y, 0.f) };
            float4 o1 = { fmaxf(v2.x, 0.f), fmaxf(v2.y, 0.f), fmaxf(v3.x, 0.f), fmaxf(v3.y, 0.f) };
            *(float4*)&node_out[(size_t)row * H + c0] = o0;
            *(float4*)&node_out[(size_t)row * H + c0 + 4] = o1;
        }
    }
}

// ---------------------------------------------------------------------------
extern "C" void kernel_launch(void* const* d_in, const int* in_sizes, int n_in,
                              void* d_out, int out_size) {
    const float* node = (const float*)d_in[0];
    const float* edge = (const float*)d_in[1];
    const int*   eidx = (const int*)d_in[2];
    const float* W1   = (const float*)d_in[3];
    const float* W2   = (const float*)d_in[4];
    const float* Wl   = (const float*)d_in[5];
    const float* e1   = (const float*)d_in[6];
    const float* e2   = (const float*)d_in[7];

    const int N = in_sizes[0] / H;
    const int E = in_sizes[1] / H;
    const int* src = eidx;
    const int* dst = eidx + E;

    float* out = (float*)d_out;
    float* node_out = out;                       // [N, H]
    float* edge_out = out + (size_t)N * H;       // [E, H]

    size_t sm0 = (size_t)(TILE * AS_LD + 2 * H * H) * sizeof(float);
    size_t sm1 = sm0 + 2 * TILE * sizeof(int);
    size_t sm2 = (size_t)(TILE * AS_LD + H * H) * sizeof(float);
    cudaFuncSetAttribute(k_node_pre, cudaFuncAttributeMaxDynamicSharedMemorySize, (int)sm0);
    cudaFuncSetAttribute(k_edge,     cudaFuncAttributeMaxDynamicSharedMemorySize, (int)sm1);
    cudaFuncSetAttribute(k_node_out, cudaFuncAttributeMaxDynamicSharedMemorySize, (int)sm2);

    int nblkN = (N + TILE - 1) / TILE;
    int nblkE = (E + TILE - 1) / TILE;

    k_node_pre<<<nblkN, NTHREADS, sm0>>>(node, W1, Wl, e1, N);
    k_edge<<<nblkE, NTHREADS, sm1>>>(edge, src, dst, W1, Wl, e2, edge_out, E);
    k_node_out<<<nblkN, NTHREADS, sm2>>>(W2, node_out, N);
}

// round 3
// speedup vs baseline: 2.5883x; 2.5883x over previous
#include <cuda_runtime.h>
#include <cuda_bf16.h>

#define H 128
#define TILE 128
#define NT 256
#define ROWB 272          // bytes per padded bf16 row (136 elems) — conflict-free ldmatrix

typedef unsigned int u32;

#define MAXN_PAD 50176
__device__ float g_P[(size_t)MAXN_PAD * H];    // node_rep @ W1_top
__device__ float g_Q[(size_t)MAXN_PAD * H];    // node_rep @ W_lift
__device__ float g_acc[(size_t)MAXN_PAD * H];  // (1+eps1)*node_rep + scatter(edge_h)

// ---------------------------------------------------------------------------
// helpers
// ---------------------------------------------------------------------------
__device__ __forceinline__ u32 pk_bf2(float lo, float hi_) {  // .h0=lo, .h1=hi
    u32 r; asm("cvt.rn.bf16x2.f32 %0, %1, %2;" : "=r"(r) : "f"(hi_), "f"(lo)); return r;
}
__device__ __forceinline__ u32 smem_u32(const void* p) {
    u32 a; asm("{ .reg .u64 t; cvta.to.shared.u64 t, %1; cvt.u32.u64 %0, t; }"
               : "=r"(a) : "l"(p)); return a;
}
__device__ __forceinline__ void red_add_v4(float* p, float a, float b, float c, float d) {
    asm volatile("red.global.add.v4.f32 [%0], {%1,%2,%3,%4};"
                 :: "l"(p), "f"(a), "f"(b), "f"(c), "f"(d) : "memory");
}
__device__ __forceinline__ void ldsm_x4(u32* r, u32 addr) {
    asm volatile("ldmatrix.sync.aligned.m8n8.x4.shared.b16 {%0,%1,%2,%3}, [%4];"
                 : "=r"(r[0]), "=r"(r[1]), "=r"(r[2]), "=r"(r[3]) : "r"(addr));
}
__device__ __forceinline__ void ldsm_x4_t(u32* r, u32 addr) {
    asm volatile("ldmatrix.sync.aligned.m8n8.x4.trans.shared.b16 {%0,%1,%2,%3}, [%4];"
                 : "=r"(r[0]), "=r"(r[1]), "=r"(r[2]), "=r"(r[3]) : "r"(addr));
}
__device__ __forceinline__ void mma_bf16(float* c, const u32* a, u32 b0, u32 b1) {
    asm volatile("mma.sync.aligned.m16n8k16.row.col.f32.bf16.bf16.f32 "
                 "{%0,%1,%2,%3}, {%4,%5,%6,%7}, {%8,%9}, {%0,%1,%2,%3};"
                 : "+f"(c[0]), "+f"(c[1]), "+f"(c[2]), "+f"(c[3])
                 : "r"(a[0]), "r"(a[1]), "r"(a[2]), "r"(a[3]), "r"(b0), "r"(b1));
}

// split fp32x4 -> bf16 hi/lo, write 8B to each buffer at byte offset boff
__device__ __forceinline__ void st_split(char* smc, int ohi, int olo, int boff, float4 v) {
    float hx = __bfloat162float(__float2bfloat16_rn(v.x));
    float hy = __bfloat162float(__float2bfloat16_rn(v.y));
    float hz = __bfloat162float(__float2bfloat16_rn(v.z));
    float hw = __bfloat162float(__float2bfloat16_rn(v.w));
    *(uint2*)(smc + ohi + boff) = make_uint2(pk_bf2(v.x, v.y), pk_bf2(v.z, v.w));
    *(uint2*)(smc + olo + boff) =
        make_uint2(pk_bf2(v.x - hx, v.y - hy), pk_bf2(v.z - hz, v.w - hw));
}

// load 128x128 fp32 W (row-major [k][n]) -> split bf16 hi/lo smem tiles
__device__ __forceinline__ void load_w(char* smc, int ohi, int olo,
                                       const float* __restrict__ W, int tid) {
    for (int i = tid; i < H * (H / 4); i += NT) {
        int k = i >> 5, c4 = (i & 31) << 2;
        float4 v = __ldg((const float4*)&W[(size_t)k * H + c4]);
        st_split(smc, ohi, olo, k * ROWB + c4 * 2, v);
    }
}

__device__ __forceinline__ void zero_acc(float acc[16][4]) {
#pragma unroll
    for (int i = 0; i < 16; i++)
#pragma unroll
        for (int j = 0; j < 4; j++) acc[i][j] = 0.f;
}

// acc += (Ahi + Alo) @ Bhi   (B fragments loaded once, used for both A passes)
__device__ __forceinline__ void gemm_dualA(u32 Ahi, u32 Alo, u32 B,
                                           float acc[16][4], int aa, int bb) {
#pragma unroll
    for (int ks = 0; ks < 8; ks++) {
        u32 ah[4], al[4];
        ldsm_x4(ah, Ahi + aa + ks * 32);
        ldsm_x4(al, Alo + aa + ks * 32);
#pragma unroll
        for (int tp = 0; tp < 8; tp++) {
            u32 b[4];
            ldsm_x4_t(b, B + bb + ks * (16 * ROWB) + tp * 32);
            mma_bf16(acc[2 * tp],     ah, b[0], b[1]);
            mma_bf16(acc[2 * tp + 1], ah, b[2], b[3]);
            mma_bf16(acc[2 * tp],     al, b[0], b[1]);
            mma_bf16(acc[2 * tp + 1], al, b[2], b[3]);
        }
    }
}
// acc += A @ B
__device__ __forceinline__ void gemm_oneA(u32 A, u32 B,
                                          float acc[16][4], int aa, int bb) {
#pragma unroll
    for (int ks = 0; ks < 8; ks++) {
        u32 a[4];
        ldsm_x4(a, A + aa + ks * 32);
#pragma unroll
        for (int tp = 0; tp < 8; tp++) {
            u32 b[4];
            ldsm_x4_t(b, B + bb + ks * (16 * ROWB) + tp * 32);
            mma_bf16(acc[2 * tp],     a, b[0], b[1]);
            mma_bf16(acc[2 * tp + 1], a, b[2], b[3]);
        }
    }
}

// repack mma fragment quad -> contiguous float4 (even lane: row q; odd: row q+8)
__device__ __forceinline__ float4 shuf_v4(const float c[4], int lane) {
    float t0 = __shfl_xor_sync(0xffffffffu, c[0], 1);
    float t1 = __shfl_xor_sync(0xffffffffu, c[1], 1);
    float t2 = __shfl_xor_sync(0xffffffffu, c[2], 1);
    float t3 = __shfl_xor_sync(0xffffffffu, c[3], 1);
    return (lane & 1) ? make_float4(t2, t3, c[2], c[3])
                      : make_float4(c[0], c[1], t0, t1);
}

// smem byte offsets
#define OFF_AHI 0
#define OFF_ALO 34816
#define OFF_B1H 69632
#define OFF_B1L 104448
#define OFF_B2H 139264
#define OFF_B2L 174080
#define SMEM_2W 208896
#define SMEM_1W 139264

// ---------------------------------------------------------------------------
// K0: P = node @ W1_top, Q = node @ W_lift, g_acc = (1+eps1)*node
// ---------------------------------------------------------------------------
extern "C" __global__ void __launch_bounds__(NT, 1)
k_node_pre(const float* __restrict__ node, const float* __restrict__ W1,
           const float* __restrict__ Wl, const float* __restrict__ eps1p,
           int N, int ntiles)
{
    extern __shared__ char smc[];
    const u32 smb = smem_u32(smc);
    const int tid = threadIdx.x, lane = tid & 31, wid = tid >> 5;
    const int wr = wid * 16;
    const float s1 = 1.f + __ldg(eps1p);

    load_w(smc, OFF_B1H, OFF_B1L, W1, tid);       // W1 top half [k<128][n]
    load_w(smc, OFF_B2H, OFF_B2L, Wl, tid);
    __syncthreads();

    const int aa = (wr + (lane & 15)) * ROWB + ((lane >> 4) << 4);
    const int bb = (lane & 15) * ROWB + ((lane >> 4) << 4);
    const int rl = (lane >> 2) + ((lane & 1) << 3);
    const int q4 = ((lane >> 1) & 1) << 2;

    for (int t = blockIdx.x; t < ntiles; t += gridDim.x) {
        const int base = t * TILE;
#pragma unroll
        for (int i = 0; i < 16; i++) {
            int r = base + wr + i;
            int rc = r < N ? r : N - 1;
            float4 v = __ldg((const float4*)&node[(size_t)rc * H + lane * 4]);
            st_split(smc, OFF_AHI, OFF_ALO, (wr + i) * ROWB + lane * 8, v);
            if (r < N) {
                float4 o = { s1 * v.x, s1 * v.y, s1 * v.z, s1 * v.w };
                *(float4*)&g_acc[(size_t)r * H + lane * 4] = o;
            }
        }
        __syncwarp();

        const int row = base + wr + rl;
        const bool valid = row < N;

        float acc[16][4];
        zero_acc(acc);
        gemm_dualA(smb + OFF_AHI, smb + OFF_ALO, smb + OFF_B1H, acc, aa, bb);
        gemm_oneA(smb + OFF_AHI, smb + OFF_B1L, acc, aa, bb);
#pragma unroll
        for (int t16 = 0; t16 < 16; t16++) {
            float4 v = shuf_v4(acc[t16], lane);
            if (valid) *(float4*)&g_P[(size_t)row * H + t16 * 8 + q4] = v;
        }

        zero_acc(acc);
        gemm_dualA(smb + OFF_AHI, smb + OFF_ALO, smb + OFF_B2H, acc, aa, bb);
        gemm_oneA(smb + OFF_AHI, smb + OFF_B2L, acc, aa, bb);
#pragma unroll
        for (int t16 = 0; t16 < 16; t16++) {
            float4 v = shuf_v4(acc[t16], lane);
            if (valid) *(float4*)&g_Q[(size_t)row * H + t16 * 8 + q4] = v;
        }
        __syncwarp();
    }
}

// ---------------------------------------------------------------------------
// K1: fused edge pipeline (persistent, warp-private tiles)
//   edge_h = relu(edge_rep @ W1_bot + P[src] + P[dst])
//   g_acc[src] += edge_h ; g_acc[dst] += edge_h          (red.v4)
//   edge_out = relu((1+eps2)*(edge_h @ W_lift) + Q[src] + Q[dst])
// ---------------------------------------------------------------------------
extern "C" __global__ void __launch_bounds__(NT, 1)
k_edge_mma(const float* __restrict__ edge_rep, const int* __restrict__ src,
           const int* __restrict__ dst, const float* __restrict__ W1,
           const float* __restrict__ Wl, const float* __restrict__ eps2p,
           float* __restrict__ edge_out, int E, int ntiles)
{
    extern __shared__ char smc[];
    const u32 smb = smem_u32(smc);
    const int tid = threadIdx.x, lane = tid & 31, wid = tid >> 5;
    const int wr = wid * 16;
    const float s2 = 1.f + __ldg(eps2p);

    load_w(smc, OFF_B1H, OFF_B1L, W1 + (size_t)H * H, tid);  // W1 bottom half
    load_w(smc, OFF_B2H, OFF_B2L, Wl, tid);
    __syncthreads();

    const int aa = (wr + (lane & 15)) * ROWB + ((lane >> 4) << 4);
    const int bb = (lane & 15) * ROWB + ((lane >> 4) << 4);
    const int rl = (lane >> 2) + ((lane & 1) << 3);
    const int q4 = ((lane >> 1) & 1) << 2;

    for (int t = blockIdx.x; t < ntiles; t += gridDim.x) {
        const int base = t * TILE;

        // A tile: warp-private rows, split bf16
#pragma unroll
        for (int i = 0; i < 16; i++) {
            int er = base + wr + i; if (er >= E) er = E - 1;
            float4 v = __ldg((const float4*)&edge_rep[(size_t)er * H + lane * 4]);
            st_split(smc, OFF_AHI, OFF_ALO, (wr + i) * ROWB + lane * 8, v);
        }
        const int er = base + wr + rl;
        const bool valid = er < E;
        const int erc = valid ? er : E - 1;
        const int s = __ldg(&src[erc]);
        const int d = __ldg(&dst[erc]);
        __syncwarp();

        // GEMM1: edge_rep @ W1_bot (3-pass split)
        float acc[16][4];
        zero_acc(acc);
        gemm_dualA(smb + OFF_AHI, smb + OFF_ALO, smb + OFF_B1H, acc, aa, bb);
        gemm_oneA(smb + OFF_AHI, smb + OFF_B1L, acc, aa, bb);

        // epilogue 1: + P gathers, relu, scatter, h -> A tile (split)
        const float* Ps = &g_P[(size_t)s * H];
        const float* Pd = &g_P[(size_t)d * H];
        float* As = &g_acc[(size_t)s * H];
        float* Ad = &g_acc[(size_t)d * H];
        const int hrow = (wr + rl) * ROWB;
#pragma unroll
        for (int t16 = 0; t16 < 16; t16++) {
            float4 v = shuf_v4(acc[t16], lane);
            const int cb = t16 * 8 + q4;
            float4 ps = __ldg((const float4*)(Ps + cb));
            float4 pd = __ldg((const float4*)(Pd + cb));
            float4 h;
            h.x = fmaxf(v.x + ps.x + pd.x, 0.f);
            h.y = fmaxf(v.y + ps.y + pd.y, 0.f);
            h.z = fmaxf(v.z + ps.z + pd.z, 0.f);
            h.w = fmaxf(v.w + ps.w + pd.w, 0.f);
            if (valid) {
                red_add_v4(As + cb, h.x, h.y, h.z, h.w);
                red_add_v4(Ad + cb, h.x, h.y, h.z, h.w);
            }
            st_split(smc, OFF_AHI, OFF_ALO, hrow + cb * 2, h);
        }
        __syncwarp();

        // GEMM2: h @ W_lift
        zero_acc(acc);
        gemm_dualA(smb + OFF_AHI, smb + OFF_ALO, smb + OFF_B2H, acc, aa, bb);
        gemm_oneA(smb + OFF_AHI, smb + OFF_B2L, acc, aa, bb);

        // epilogue 2: + Q gathers, scale, relu, store
        const float* Qs = &g_Q[(size_t)s * H];
        const float* Qd = &g_Q[(size_t)d * H];
        float* op = &edge_out[(size_t)er * H];
#pragma unroll
        for (int t16 = 0; t16 < 16; t16++) {
            float4 v = shuf_v4(acc[t16], lane);
            const int cb = t16 * 8 + q4;
            float4 qs = __ldg((const float4*)(Qs + cb));
            float4 qd = __ldg((const float4*)(Qd + cb));
            float4 o;
            o.x = fmaxf(fmaf(s2, v.x, qs.x + qd.x), 0.f);
            o.y = fmaxf(fmaf(s2, v.y, qs.y + qd.y), 0.f);
            o.z = fmaxf(fmaf(s2, v.z, qs.z + qd.z), 0.f);
            o.w = fmaxf(fmaf(s2, v.w, qs.w + qd.w), 0.f);
            if (valid) *(float4*)(op + cb) = o;
        }
        __syncwarp();
    }
}

// ---------------------------------------------------------------------------
// K2: node_out = relu(g_acc @ W2)
// ---------------------------------------------------------------------------
extern "C" __global__ void __launch_bounds__(NT, 1)
k_node_out(const float* __restrict__ W2, float* __restrict__ node_out,
           int N, int ntiles)
{
    extern __shared__ char smc[];
    const u32 smb = smem_u32(smc);
    const int tid = threadIdx.x, lane = tid & 31, wid = tid >> 5;
    const int wr = wid * 16;

    load_w(smc, OFF_B1H, OFF_B1L, W2, tid);
    __syncthreads();

    const int aa = (wr + (lane & 15)) * ROWB + ((lane >> 4) << 4);
    const int bb = (lane & 15) * ROWB + ((lane >> 4) << 4);
    const int rl = (lane >> 2) + ((lane & 1) << 3);
    const int q4 = ((lane >> 1) & 1) << 2;

    for (int t = blockIdx.x; t < ntiles; t += gridDim.x) {
        const int base = t * TILE;
#pragma unroll
        for (int i = 0; i < 16; i++) {
            int r = base + wr + i; if (r >= N) r = N - 1;
            float4 v = *(const float4*)&g_acc[(size_t)r * H + lane * 4];
            st_split(smc, OFF_AHI, OFF_ALO, (wr + i) * ROWB + lane * 8, v);
        }
        __syncwarp();

        const int row = base + wr + rl;
        const bool valid = row < N;

        float acc[16][4];
        zero_acc(acc);
        gemm_dualA(smb + OFF_AHI, smb + OFF_ALO, smb + OFF_B1H, acc, aa, bb);
        gemm_oneA(smb + OFF_AHI, smb + OFF_B1L, acc, aa, bb);
#pragma unroll
        for (int t16 = 0; t16 < 16; t16++) {
            float4 v = shuf_v4(acc[t16], lane);
            float4 o = { fmaxf(v.x, 0.f), fmaxf(v.y, 0.f),
                         fmaxf(v.z, 0.f), fmaxf(v.w, 0.f) };
            if (valid) *(float4*)&node_out[(size_t)row * H + t16 * 8 + q4] = o;
        }
        __syncwarp();
    }
}

// ---------------------------------------------------------------------------
extern "C" void kernel_launch(void* const* d_in, const int* in_sizes, int n_in,
                              void* d_out, int out_size) {
    const float* node = (const float*)d_in[0];
    const float* edge = (const float*)d_in[1];
    const int*   eidx = (const int*)d_in[2];
    const float* W1   = (const float*)d_in[3];
    const float* W2   = (const float*)d_in[4];
    const float* Wl   = (const float*)d_in[5];
    const float* e1   = (const float*)d_in[6];
    const float* e2   = (const float*)d_in[7];

    const int N = in_sizes[0] / H;
    const int E = in_sizes[1] / H;
    const int* src = eidx;
    const int* dst = eidx + E;

    float* out = (float*)d_out;
    float* node_out = out;                       // [N, H]
    float* edge_out = out + (size_t)N * H;       // [E, H]

    cudaFuncSetAttribute(k_node_pre, cudaFuncAttributeMaxDynamicSharedMemorySize, SMEM_2W);
    cudaFuncSetAttribute(k_edge_mma, cudaFuncAttributeMaxDynamicSharedMemorySize, SMEM_2W);
    cudaFuncSetAttribute(k_node_out, cudaFuncAttributeMaxDynamicSharedMemorySize, SMEM_1W);

    int nsm = 148;
    cudaDeviceGetAttribute(&nsm, cudaDevAttrMultiProcessorCount, 0);

    int ntN = (N + TILE - 1) / TILE;
    int ntE = (E + TILE - 1) / TILE;
    int gridE = ntE < nsm ? ntE : nsm;

    k_node_pre<<<ntN, NT, SMEM_2W>>>(node, W1, Wl, e1, N, ntN);
    k_edge_mma<<<gridE, NT, SMEM_2W>>>(edge, src, dst, W1, Wl, e2, edge_out, E, ntE);
    k_node_out<<<ntN, NT, SMEM_1W>>>(W2, node_out, N, ntN);
}